// round 6
// baseline (speedup 1.0000x reference)
#include <cuda_runtime.h>
#include <math.h>

#define Nn   50000
#define Ee   800000
#define EPt  850000   // E + N self loops
#define Gg   64
#define NBLK 49       // ceil(Nn/1024)

// ---------------- scratch ----------------
__device__ __align__(16) float g_h1   [(size_t)Nn*128];
__device__ __align__(16) float g_out1 [(size_t)Nn*128];
__device__ __align__(16) float g_h2   [(size_t)Nn*64];
__device__ __align__(16) float g_asrc1[Nn*4];
__device__ __align__(16) float g_adst1[Nn*4];
__device__ __align__(16) float g_asrc2[Nn];
__device__ __align__(16) float g_adst2[Nn];
__device__ __align__(16) float g_tae1 [(size_t)Ee*4];  // unsorted a_edge L1
__device__ __align__(16) float g_tae2 [Ee];            // unsorted a_edge L2
__device__ __align__(16) int   g_ssrc [EPt];           // sorted-by-dst src
__device__ __align__(16) float g_sae1 [(size_t)EPt*4]; // sorted a_edge L1
__device__ __align__(16) float g_sae2 [EPt];           // sorted a_edge L2
__device__ __align__(16) int   g_deg  [Nn];
__device__ __align__(16) int   g_off  [Nn+1];
__device__ __align__(16) int   g_cur  [Nn];
__device__ __align__(16) int   g_bsum [NBLK];
__device__ __align__(16) int   g_boff [NBLK];
__device__ __align__(16) float g_sum_ea[16];
__device__ __align__(16) float g_v1[64];
__device__ __align__(16) float g_v2[16];
__device__ __align__(16) float g_lae1[4];
__device__ __align__(16) float g_lae2[1];
__device__ __align__(16) float g_pool[Gg*64];
__device__ __align__(16) int   g_cnt [Gg];

__device__ __forceinline__ float lrelu(float x){ return x > 0.f ? x : 0.2f*x; }

// packed f32x2 helpers (sm_100+)
__device__ __forceinline__ void ffma2(unsigned long long& d, unsigned long long a, unsigned long long b){
    asm("fma.rn.f32x2 %0, %1, %2, %0;" : "+l"(d) : "l"(a), "l"(b));
}
__device__ __forceinline__ unsigned long long bcast2(float a){
    unsigned long long r;
    asm("mov.b64 %0, {%1, %1};" : "=l"(r) : "f"(a));
    return r;
}

// ---------------- 1. v1/v2 from weights only ----------------
__global__ void k_v(const float* __restrict__ We1, const float* __restrict__ ae1,
                    const float* __restrict__ We2, const float* __restrict__ ae2){
    int t = threadIdx.x;
    {
        int h = t >> 4, d = t & 15;
        float s = 0.f;
        for(int c=0;c<32;c++) s += We1[d*128 + h*32 + c] * ae1[h*32 + c];
        g_v1[h*16 + d] = s;
    }
    if(t < 16){
        float s = 0.f;
        for(int c=0;c<64;c++) s += We2[t*64 + c] * ae2[c];
        g_v2[t] = s;
    }
}

// ---------------- 2. pass1: hist + sum_ea + a_edge dots into temp ----------------
__global__ void k_pass1(const float* __restrict__ ea, const int* __restrict__ ei){
    __shared__ float sv1[64], sv2[16];
    int t = threadIdx.x;
    if(t < 64) sv1[t] = g_v1[t];
    if(t < 16) sv2[t] = g_v2[t];
    __syncthreads();
    float acc[16];
#pragma unroll
    for(int i=0;i<16;i++) acc[i]=0.f;
    int stride = gridDim.x*blockDim.x;
    for(int e = blockIdx.x*blockDim.x + t; e < EPt; e += stride){
        int d = (e < Ee) ? __ldg(&ei[Ee + e]) : (e - Ee);
        atomicAdd(&g_deg[d], 1);
        if(e < Ee){
            float r[16];
            const float4* rp = (const float4*)(ea + (size_t)e*16);
            ((float4*)r)[0]=__ldg(rp);   ((float4*)r)[1]=__ldg(rp+1);
            ((float4*)r)[2]=__ldg(rp+2); ((float4*)r)[3]=__ldg(rp+3);
#pragma unroll
            for(int i=0;i<16;i++) acc[i] += r[i];
            float ae[4];
#pragma unroll
            for(int h=0;h<4;h++){
                float a=0.f;
#pragma unroll
                for(int i=0;i<16;i++) a += sv1[h*16+i]*r[i];
                ae[h]=a;
            }
            float a2=0.f;
#pragma unroll
            for(int i=0;i<16;i++) a2 += sv2[i]*r[i];
            *(float4*)&g_tae1[(size_t)e*4] = make_float4(ae[0],ae[1],ae[2],ae[3]);
            g_tae2[e] = a2;
        }
    }
#pragma unroll
    for(int off=16; off; off>>=1)
#pragma unroll
        for(int i=0;i<16;i++) acc[i] += __shfl_xor_sync(0xffffffffu, acc[i], off);
    if((t & 31)==0)
#pragma unroll
        for(int i=0;i<16;i++) atomicAdd(&g_sum_ea[i], acc[i]);
}

// ---------------- 3. scan (3 kernels, warp-shuffle); lae folded into scanB ----------------
__global__ void k_scanA(){
    __shared__ int wsum[8], wexc[8];
    int t = threadIdx.x, blk = blockIdx.x;
    int base = blk*1024 + t*4;
    int v0 = (base+0<Nn)?g_deg[base+0]:0;
    int v1 = (base+1<Nn)?g_deg[base+1]:0;
    int v2 = (base+2<Nn)?g_deg[base+2]:0;
    int v3 = (base+3<Nn)?g_deg[base+3]:0;
    int s = v0+v1+v2+v3;
    int lane = t&31, w = t>>5;
    int ps = s;
#pragma unroll
    for(int off=1; off<32; off<<=1){
        int n = __shfl_up_sync(0xffffffffu, ps, off);
        if(lane>=off) ps += n;
    }
    if(lane==31) wsum[w] = ps;
    __syncthreads();
    if(t==0){
        int r=0;
#pragma unroll
        for(int k=0;k<8;k++){ wexc[k]=r; r+=wsum[k]; }
        g_bsum[blk]=r;
    }
    __syncthreads();
    int run = wexc[w] + ps - s;
    if(base+0<Nn) g_off[base+0]=run; run+=v0;
    if(base+1<Nn) g_off[base+1]=run; run+=v1;
    if(base+2<Nn) g_off[base+2]=run; run+=v2;
    if(base+3<Nn) g_off[base+3]=run;
}
__global__ void k_scanB(){
    int t = threadIdx.x;
    if(t==0){
        int r=0;
        for(int b=0;b<NBLK;b++){ g_boff[b]=r; r+=g_bsum[b]; }
        g_off[Nn]=EPt;
    }
    if(t>=1 && t<5){
        int h = t-1;
        float s = 0.f;
        for(int d=0;d<16;d++) s += (g_sum_ea[d]*(1.0f/(float)Ee))*g_v1[h*16+d];
        g_lae1[h] = s;
    }
    if(t == 5){
        float s = 0.f;
        for(int d=0;d<16;d++) s += (g_sum_ea[d]*(1.0f/(float)Ee))*g_v2[d];
        g_lae2[0] = s;
    }
}
__global__ void k_scanC(){
    int blk = blockIdx.x;
    if(blk==0) return;
    int add = g_boff[blk];
    int base = blk*1024 + threadIdx.x*4;
#pragma unroll
    for(int j=0;j<4;j++)
        if(base+j < Nn) g_off[base+j] += add;
}

// ---------------- 4. scatter (pure permute) ----------------
__global__ void k_scatter(const int* __restrict__ ei){
    int e = blockIdx.x*blockDim.x + threadIdx.x;
    if(e >= EPt) return;
    int s, d; float4 ae; float ae2;
    if(e < Ee){
        s = __ldg(&ei[e]); d = __ldg(&ei[Ee + e]);
        ae = *(const float4*)&g_tae1[(size_t)e*4];
        ae2 = g_tae2[e];
    } else {
        s = d = e - Ee;
        ae = make_float4(g_lae1[0],g_lae1[1],g_lae1[2],g_lae1[3]);
        ae2 = g_lae2[0];
    }
    int pos = g_off[d] + atomicAdd(&g_cur[d], 1);
    g_ssrc[pos] = s;
    *(float4*)&g_sae1[(size_t)pos*4] = ae;
    g_sae2[pos] = ae2;
}

// ---------------- 5. SGEMM (K=128) with f32x2 inner loop + fused a_src/a_dst epilogue ----------------
template<int NC, bool ELU>
__global__ __launch_bounds__(256) void k_gemm(const float* __restrict__ A,
                                              const float* __restrict__ W,
                                              const float* __restrict__ abias,
                                              const float* __restrict__ atts,
                                              const float* __restrict__ attd,
                                              float* __restrict__ C,
                                              float* __restrict__ oasrc,
                                              float* __restrict__ oadst, int M){
    constexpr int CPT = NC/16;                 // cols per thread (8 or 4)
    constexpr int CP2 = CPT/2;                 // col pairs (4 or 2)
    __shared__ float As[64*36];
    __shared__ float Ws[32*NC];
    __shared__ float as_s[NC], ad_s[NC];
    const int t  = threadIdx.x;
    const int rg = t >> 4, cg = t & 15;
    const int r0 = blockIdx.x * 64;
    if(t < NC){ as_s[t]=__ldg(&atts[t]); ad_s[t]=__ldg(&attd[t]); }
    unsigned long long accp[4][CP2];
#pragma unroll
    for(int i=0;i<4;i++)
#pragma unroll
        for(int j=0;j<CP2;j++) accp[i][j]=0ull;

    for(int kc=0; kc<128; kc+=32){
#pragma unroll
        for(int i=0;i<2;i++){
            int f = t + i*256; int r = f>>3; int c4 = f&7;
            float4 v = make_float4(0.f,0.f,0.f,0.f);
            if(r0 + r < M) v = __ldg((const float4*)&A[(size_t)(r0+r)*128 + kc + c4*4]);
            if(ELU){
                float4 bb = __ldg((const float4*)&abias[kc + c4*4]);
                v.x += bb.x; v.y += bb.y; v.z += bb.z; v.w += bb.w;
                v.x = v.x>0.f ? v.x : expm1f(v.x);
                v.y = v.y>0.f ? v.y : expm1f(v.y);
                v.z = v.z>0.f ? v.z : expm1f(v.z);
                v.w = v.w>0.f ? v.w : expm1f(v.w);
            }
            float* dst = &As[r*36 + c4*4];
            dst[0]=v.x; dst[1]=v.y; dst[2]=v.z; dst[3]=v.w;
        }
#pragma unroll
        for(int f=t; f < 32*NC/4; f += 256){
            int k = f/(NC/4); int c = f%(NC/4);
            *(float4*)&Ws[k*NC + c*4] = __ldg((const float4*)&W[(size_t)(kc+k)*NC + c*4]);
        }
        __syncthreads();
#pragma unroll 4
        for(int kk=0; kk<32; kk++){
            unsigned long long a0 = bcast2(As[(rg*4+0)*36+kk]);
            unsigned long long a1 = bcast2(As[(rg*4+1)*36+kk]);
            unsigned long long a2 = bcast2(As[(rg*4+2)*36+kk]);
            unsigned long long a3 = bcast2(As[(rg*4+3)*36+kk]);
            const unsigned long long* bp =
                (const unsigned long long*)&Ws[kk*NC + cg*CPT];
#pragma unroll
            for(int j=0;j<CP2;j++){
                unsigned long long b = bp[j];
                ffma2(accp[0][j], a0, b);
                ffma2(accp[1][j], a1, b);
                ffma2(accp[2][j], a2, b);
                ffma2(accp[3][j], a3, b);
            }
        }
        __syncthreads();
    }
#pragma unroll
    for(int i=0;i<4;i++){
        int row = r0 + rg*4 + i;
        float c[CPT];
#pragma unroll
        for(int j=0;j<CP2;j++){
            float2 u = *(float2*)&accp[i][j];
            c[2*j]=u.x; c[2*j+1]=u.y;
        }
        float ps=0.f, pd=0.f;
#pragma unroll
        for(int j=0;j<CPT;j++){
            ps += c[j]*as_s[cg*CPT+j]; pd += c[j]*ad_s[cg*CPT+j];
        }
        if constexpr (NC == 128){
            ps += __shfl_xor_sync(0xffffffffu, ps, 1); pd += __shfl_xor_sync(0xffffffffu, pd, 1);
            ps += __shfl_xor_sync(0xffffffffu, ps, 2); pd += __shfl_xor_sync(0xffffffffu, pd, 2);
            if((cg&3)==0 && row<M){ oasrc[row*4+(cg>>2)]=ps; oadst[row*4+(cg>>2)]=pd; }
        } else {
            ps += __shfl_xor_sync(0xffffffffu, ps, 1); pd += __shfl_xor_sync(0xffffffffu, pd, 1);
            ps += __shfl_xor_sync(0xffffffffu, ps, 2); pd += __shfl_xor_sync(0xffffffffu, pd, 2);
            ps += __shfl_xor_sync(0xffffffffu, ps, 4); pd += __shfl_xor_sync(0xffffffffu, pd, 4);
            ps += __shfl_xor_sync(0xffffffffu, ps, 8); pd += __shfl_xor_sync(0xffffffffu, pd, 8);
            if(cg==0 && row<M){ oasrc[row]=ps; oadst[row]=pd; }
        }
        if(row < M){
#pragma unroll
            for(int j4=0; j4<CPT; j4+=4){
                float4 v = make_float4(c[j4],c[j4+1],c[j4+2],c[j4+3]);
                *(float4*)&C[(size_t)row*NC + cg*CPT + j4] = v;
            }
        }
    }
}

// ---------------- 6. fused layer-1: online softmax + aggregate (warp/node, x4 unroll) ----------------
#define COMB1(a, hv) { \
    if((a) <= m){ float w=__expf((a)-m); sden+=w; \
        acc.x+=hv.x*w; acc.y+=hv.y*w; acc.z+=hv.z*w; acc.w+=hv.w*w; } \
    else { float sc=__expf(m-(a)); sden=sden*sc+1.f; \
        acc.x=acc.x*sc+hv.x; acc.y=acc.y*sc+hv.y; acc.z=acc.z*sc+hv.z; acc.w=acc.w*sc+hv.w; m=(a);} }

__global__ __launch_bounds__(256) void k_layer1(){
    int lane = threadIdx.x & 31;
    int d = (blockIdx.x*blockDim.x + threadIdx.x) >> 5;
    if(d >= Nn) return;
    int beg = g_off[d], end = g_off[d+1];
    int h = lane >> 3;
    float adst = __ldg(&g_adst1[d*4+h]);
    float m = -1e30f, sden = 0.f;
    float4 acc = make_float4(0.f,0.f,0.f,0.f);
    int i = beg;
    for(; i+4 <= end; i+=4){
        int s0=__ldg(&g_ssrc[i+0]), s1=__ldg(&g_ssrc[i+1]),
            s2=__ldg(&g_ssrc[i+2]), s3=__ldg(&g_ssrc[i+3]);
        float e0=__ldg(&g_sae1[(size_t)(i+0)*4+h]), e1=__ldg(&g_sae1[(size_t)(i+1)*4+h]),
              e2=__ldg(&g_sae1[(size_t)(i+2)*4+h]), e3=__ldg(&g_sae1[(size_t)(i+3)*4+h]);
        float a0=lrelu(__ldg(&g_asrc1[s0*4+h])+adst+e0);
        float a1=lrelu(__ldg(&g_asrc1[s1*4+h])+adst+e1);
        float a2=lrelu(__ldg(&g_asrc1[s2*4+h])+adst+e2);
        float a3=lrelu(__ldg(&g_asrc1[s3*4+h])+adst+e3);
        float4 v0=__ldg((const float4*)&g_h1[(size_t)s0*128+lane*4]);
        float4 v1=__ldg((const float4*)&g_h1[(size_t)s1*128+lane*4]);
        float4 v2=__ldg((const float4*)&g_h1[(size_t)s2*128+lane*4]);
        float4 v3=__ldg((const float4*)&g_h1[(size_t)s3*128+lane*4]);
        COMB1(a0,v0); COMB1(a1,v1); COMB1(a2,v2); COMB1(a3,v3);
    }
    for(; i<end; i++){
        int s = __ldg(&g_ssrc[i]);
        float a = lrelu(__ldg(&g_asrc1[s*4+h])+adst+__ldg(&g_sae1[(size_t)i*4+h]));
        float4 hv = __ldg((const float4*)&g_h1[(size_t)s*128+lane*4]);
        COMB1(a,hv);
    }
    float inv = 1.f/sden;
    *(float4*)&g_out1[(size_t)d*128 + lane*4] =
        make_float4(acc.x*inv, acc.y*inv, acc.z*inv, acc.w*inv);
}

// ---------------- 7. fused layer-2 + pool (warp/node, float2, x4 unroll) ----------------
#define COMB2(a, hv) { \
    if((a) <= m){ float w=__expf((a)-m); sden+=w; acc.x+=hv.x*w; acc.y+=hv.y*w; } \
    else { float sc=__expf(m-(a)); sden=sden*sc+1.f; \
        acc.x=acc.x*sc+hv.x; acc.y=acc.y*sc+hv.y; m=(a);} }

__global__ __launch_bounds__(256) void k_layer2(const int* __restrict__ batch){
    int lane = threadIdx.x & 31;
    int d = (blockIdx.x*blockDim.x + threadIdx.x) >> 5;
    if(d >= Nn) return;
    int beg = g_off[d], end = g_off[d+1];
    float adst = __ldg(&g_adst2[d]);
    float m = -1e30f, sden = 0.f;
    float2 acc = make_float2(0.f,0.f);
    int i = beg;
    for(; i+4 <= end; i+=4){
        int s0=__ldg(&g_ssrc[i+0]), s1=__ldg(&g_ssrc[i+1]),
            s2=__ldg(&g_ssrc[i+2]), s3=__ldg(&g_ssrc[i+3]);
        float a0=lrelu(__ldg(&g_asrc2[s0])+adst+__ldg(&g_sae2[i+0]));
        float a1=lrelu(__ldg(&g_asrc2[s1])+adst+__ldg(&g_sae2[i+1]));
        float a2=lrelu(__ldg(&g_asrc2[s2])+adst+__ldg(&g_sae2[i+2]));
        float a3=lrelu(__ldg(&g_asrc2[s3])+adst+__ldg(&g_sae2[i+3]));
        float2 v0=__ldg((const float2*)&g_h2[(size_t)s0*64+lane*2]);
        float2 v1=__ldg((const float2*)&g_h2[(size_t)s1*64+lane*2]);
        float2 v2=__ldg((const float2*)&g_h2[(size_t)s2*64+lane*2]);
        float2 v3=__ldg((const float2*)&g_h2[(size_t)s3*64+lane*2]);
        COMB2(a0,v0); COMB2(a1,v1); COMB2(a2,v2); COMB2(a3,v3);
    }
    for(; i<end; i++){
        int s = __ldg(&g_ssrc[i]);
        float a = lrelu(__ldg(&g_asrc2[s])+adst+__ldg(&g_sae2[i]));
        float2 hv = __ldg((const float2*)&g_h2[(size_t)s*64+lane*2]);
        COMB2(a,hv);
    }
    float inv = 1.f/sden;
    int g = __ldg(&batch[d]);
    atomicAdd((float2*)&g_pool[g*64 + lane*2], make_float2(acc.x*inv, acc.y*inv));
    if(lane==0) atomicAdd(&g_cnt[g], 1);
}

// ---------------- 8. final: mean + bias ----------------
__global__ void k_final(float* __restrict__ out, const float* __restrict__ b2){
    int i = blockIdx.x*blockDim.x + threadIdx.x;
    if(i >= Gg*64) return;
    out[i] = g_pool[i] / fmaxf((float)g_cnt[i >> 6], 1.0f) + __ldg(&b2[i & 63]);
}

// ---------------- host launcher ----------------
extern "C" void kernel_launch(void* const* d_in, const int* in_sizes, int n_in,
                              void* d_out, int out_size){
    (void)in_sizes; (void)n_in; (void)out_size;
    const float* x     = (const float*)d_in[0];
    const int*   ei    = (const int*)d_in[1];
    const float* ea    = (const float*)d_in[2];
    const int*   batch = (const int*)d_in[3];
    const float* W1    = (const float*)d_in[4];
    const float* as1   = (const float*)d_in[5];
    const float* ad1   = (const float*)d_in[6];
    const float* We1   = (const float*)d_in[7];
    const float* ae1   = (const float*)d_in[8];
    const float* b1    = (const float*)d_in[9];
    const float* W2    = (const float*)d_in[10];
    const float* as2   = (const float*)d_in[11];
    const float* ad2   = (const float*)d_in[12];
    const float* We2   = (const float*)d_in[13];
    const float* ae2   = (const float*)d_in[14];
    const float* b2    = (const float*)d_in[15];
    float*       out   = (float*)d_out;

    void *p_deg,*p_cur,*p_sum,*p_pool,*p_cnt,*p_h1,*p_out1,*p_h2;
    void *p_asrc1,*p_adst1,*p_asrc2,*p_adst2;
    cudaGetSymbolAddress(&p_deg,  g_deg);
    cudaGetSymbolAddress(&p_cur,  g_cur);
    cudaGetSymbolAddress(&p_sum,  g_sum_ea);
    cudaGetSymbolAddress(&p_pool, g_pool);
    cudaGetSymbolAddress(&p_cnt,  g_cnt);
    cudaGetSymbolAddress(&p_h1,   g_h1);
    cudaGetSymbolAddress(&p_out1, g_out1);
    cudaGetSymbolAddress(&p_h2,   g_h2);
    cudaGetSymbolAddress(&p_asrc1, g_asrc1);
    cudaGetSymbolAddress(&p_adst1, g_adst1);
    cudaGetSymbolAddress(&p_asrc2, g_asrc2);
    cudaGetSymbolAddress(&p_adst2, g_adst2);

    cudaStream_t s2;
    cudaEvent_t evFork, evJoin;
    cudaStreamCreateWithFlags(&s2, cudaStreamNonBlocking);
    cudaEventCreateWithFlags(&evFork, cudaEventDisableTiming);
    cudaEventCreateWithFlags(&evJoin, cudaEventDisableTiming);

    cudaMemsetAsync(p_deg, 0, Nn*sizeof(int));
    cudaMemsetAsync(p_cur, 0, Nn*sizeof(int));
    cudaMemsetAsync(p_sum, 0, 16*sizeof(float));
    cudaMemsetAsync(p_pool,0, Gg*64*sizeof(float));
    cudaMemsetAsync(p_cnt, 0, Gg*sizeof(int));

    // fork: GEMM1 runs concurrently with edge preprocessing
    cudaEventRecord(evFork, 0);
    cudaStreamWaitEvent(s2, evFork, 0);
    k_gemm<128,false><<<(Nn+63)/64, 256, 0, s2>>>(x, W1, nullptr, as1, ad1,
                                           (float*)p_h1, (float*)p_asrc1, (float*)p_adst1, Nn);
    cudaEventRecord(evJoin, s2);

    // edge preprocessing on origin stream
    k_v<<<1, 64>>>(We1, ae1, We2, ae2);
    k_pass1<<<592, 256>>>(ea, ei);
    k_scanA<<<NBLK, 256>>>();
    k_scanB<<<1, 32>>>();
    k_scanC<<<NBLK, 256>>>();
    k_scatter<<<(EPt+255)/256, 256>>>(ei);

    // join: layer1 needs both gemm1 (h1/asrc1/adst1) and scatter (CSR)
    cudaStreamWaitEvent(0, evJoin, 0);
    k_layer1<<<(Nn*32+255)/256, 256>>>();

    k_gemm<64,true><<<(Nn+63)/64, 256>>>((float*)p_out1, W2, b1, as2, ad2,
                                         (float*)p_h2, (float*)p_asrc2, (float*)p_adst2, Nn);
    k_layer2<<<(Nn*32+255)/256, 256>>>(batch);

    k_final<<<(Gg*64+255)/256, 256>>>(out, b2);
}

// round 7
// speedup vs baseline: 1.0368x; 1.0368x over previous
#include <cuda_runtime.h>
#include <cuda_fp16.h>
#include <math.h>

#define Nn   50000
#define Ee   800000
#define EPt  850000   // E + N self loops
#define Gg   64
#define NBLK 49       // ceil(Nn/1024)

// ---------------- scratch ----------------
__device__ __align__(16) __half g_h1  [(size_t)Nn*128];   // fp16 features L1
__device__ __align__(16) float  g_out1[(size_t)Nn*128];
__device__ __align__(16) __half g_h2  [(size_t)Nn*64];    // fp16 features L2
__device__ __align__(16) float  g_asrc1[Nn*4];
__device__ __align__(16) float  g_adst1[Nn*4];
__device__ __align__(16) float  g_asrc2[Nn];
__device__ __align__(16) float  g_adst2[Nn];
__device__ __align__(16) float  g_tae1 [(size_t)Ee*4];
__device__ __align__(16) float  g_tae2 [Ee];
__device__ __align__(16) int    g_ssrc [EPt];
__device__ __align__(16) float  g_sae1 [(size_t)EPt*4];
__device__ __align__(16) float  g_sae2 [EPt];
__device__ __align__(16) int    g_deg  [Nn];
__device__ __align__(16) int    g_off  [Nn+1];
__device__ __align__(16) int    g_cur  [Nn];
__device__ __align__(16) int    g_bsum [NBLK];
__device__ __align__(16) int    g_boff [NBLK];
__device__ __align__(16) float  g_sum_ea[16];
__device__ __align__(16) float  g_v1[64];
__device__ __align__(16) float  g_v2[16];
__device__ __align__(16) float  g_lae1[4];
__device__ __align__(16) float  g_lae2[1];
__device__ __align__(16) float  g_pool[Gg*64];
__device__ __align__(16) int    g_cnt [Gg];

__device__ __forceinline__ float lrelu(float x){ return x > 0.f ? x : 0.2f*x; }

// load 4 contiguous halfs -> float4
__device__ __forceinline__ float4 ldh4(const __half* p){
    uint2 u = __ldg((const uint2*)p);
    float2 a = __half22float2(*(__half2*)&u.x);
    float2 b = __half22float2(*(__half2*)&u.y);
    return make_float4(a.x, a.y, b.x, b.y);
}
// load 2 contiguous halfs -> float2
__device__ __forceinline__ float2 ldh2(const __half* p){
    unsigned u = __ldg((const unsigned*)p);
    return __half22float2(*(__half2*)&u);
}

// ---------------- 1. v1/v2 from weights only ----------------
__global__ void k_v(const float* __restrict__ We1, const float* __restrict__ ae1,
                    const float* __restrict__ We2, const float* __restrict__ ae2){
    int t = threadIdx.x;
    {
        int h = t >> 4, d = t & 15;
        float s = 0.f;
        for(int c=0;c<32;c++) s += We1[d*128 + h*32 + c] * ae1[h*32 + c];
        g_v1[h*16 + d] = s;
    }
    if(t < 16){
        float s = 0.f;
        for(int c=0;c<64;c++) s += We2[t*64 + c] * ae2[c];
        g_v2[t] = s;
    }
}

// ---------------- 2. pass1: hist + sum_ea + a_edge dots into temp ----------------
__global__ void k_pass1(const float* __restrict__ ea, const int* __restrict__ ei){
    __shared__ float sv1[64], sv2[16];
    int t = threadIdx.x;
    if(t < 64) sv1[t] = g_v1[t];
    if(t < 16) sv2[t] = g_v2[t];
    __syncthreads();
    float acc[16];
#pragma unroll
    for(int i=0;i<16;i++) acc[i]=0.f;
    int stride = gridDim.x*blockDim.x;
    for(int e = blockIdx.x*blockDim.x + t; e < EPt; e += stride){
        int d = (e < Ee) ? __ldg(&ei[Ee + e]) : (e - Ee);
        atomicAdd(&g_deg[d], 1);
        if(e < Ee){
            float r[16];
            const float4* rp = (const float4*)(ea + (size_t)e*16);
            ((float4*)r)[0]=__ldg(rp);   ((float4*)r)[1]=__ldg(rp+1);
            ((float4*)r)[2]=__ldg(rp+2); ((float4*)r)[3]=__ldg(rp+3);
#pragma unroll
            for(int i=0;i<16;i++) acc[i] += r[i];
            float ae[4];
#pragma unroll
            for(int h=0;h<4;h++){
                float a=0.f;
#pragma unroll
                for(int i=0;i<16;i++) a += sv1[h*16+i]*r[i];
                ae[h]=a;
            }
            float a2=0.f;
#pragma unroll
            for(int i=0;i<16;i++) a2 += sv2[i]*r[i];
            *(float4*)&g_tae1[(size_t)e*4] = make_float4(ae[0],ae[1],ae[2],ae[3]);
            g_tae2[e] = a2;
        }
    }
#pragma unroll
    for(int off=16; off; off>>=1)
#pragma unroll
        for(int i=0;i<16;i++) acc[i] += __shfl_xor_sync(0xffffffffu, acc[i], off);
    if((t & 31)==0)
#pragma unroll
        for(int i=0;i<16;i++) atomicAdd(&g_sum_ea[i], acc[i]);
}

// ---------------- 3. scan (3 kernels, warp-shuffle); lae folded into scanB ----------------
__global__ void k_scanA(){
    __shared__ int wsum[8], wexc[8];
    int t = threadIdx.x, blk = blockIdx.x;
    int base = blk*1024 + t*4;
    int v0 = (base+0<Nn)?g_deg[base+0]:0;
    int v1 = (base+1<Nn)?g_deg[base+1]:0;
    int v2 = (base+2<Nn)?g_deg[base+2]:0;
    int v3 = (base+3<Nn)?g_deg[base+3]:0;
    int s = v0+v1+v2+v3;
    int lane = t&31, w = t>>5;
    int ps = s;
#pragma unroll
    for(int off=1; off<32; off<<=1){
        int n = __shfl_up_sync(0xffffffffu, ps, off);
        if(lane>=off) ps += n;
    }
    if(lane==31) wsum[w] = ps;
    __syncthreads();
    if(t==0){
        int r=0;
#pragma unroll
        for(int k=0;k<8;k++){ wexc[k]=r; r+=wsum[k]; }
        g_bsum[blk]=r;
    }
    __syncthreads();
    int run = wexc[w] + ps - s;
    if(base+0<Nn) g_off[base+0]=run; run+=v0;
    if(base+1<Nn) g_off[base+1]=run; run+=v1;
    if(base+2<Nn) g_off[base+2]=run; run+=v2;
    if(base+3<Nn) g_off[base+3]=run;
}
__global__ void k_scanB(){
    int t = threadIdx.x;
    if(t==0){
        int r=0;
        for(int b=0;b<NBLK;b++){ g_boff[b]=r; r+=g_bsum[b]; }
        g_off[Nn]=EPt;
    }
    if(t>=1 && t<5){
        int h = t-1;
        float s = 0.f;
        for(int d=0;d<16;d++) s += (g_sum_ea[d]*(1.0f/(float)Ee))*g_v1[h*16+d];
        g_lae1[h] = s;
    }
    if(t == 5){
        float s = 0.f;
        for(int d=0;d<16;d++) s += (g_sum_ea[d]*(1.0f/(float)Ee))*g_v2[d];
        g_lae2[0] = s;
    }
}
__global__ void k_scanC(){
    int blk = blockIdx.x;
    if(blk==0) return;
    int add = g_boff[blk];
    int base = blk*1024 + threadIdx.x*4;
#pragma unroll
    for(int j=0;j<4;j++)
        if(base+j < Nn) g_off[base+j] += add;
}

// ---------------- 4. scatter (pure permute) ----------------
__global__ void k_scatter(const int* __restrict__ ei){
    int e = blockIdx.x*blockDim.x + threadIdx.x;
    if(e >= EPt) return;
    int s, d; float4 ae; float ae2;
    if(e < Ee){
        s = __ldg(&ei[e]); d = __ldg(&ei[Ee + e]);
        ae = *(const float4*)&g_tae1[(size_t)e*4];
        ae2 = g_tae2[e];
    } else {
        s = d = e - Ee;
        ae = make_float4(g_lae1[0],g_lae1[1],g_lae1[2],g_lae1[3]);
        ae2 = g_lae2[0];
    }
    int pos = g_off[d] + atomicAdd(&g_cur[d], 1);
    g_ssrc[pos] = s;
    *(float4*)&g_sae1[(size_t)pos*4] = ae;
    g_sae2[pos] = ae2;
}

// ---------------- 5. SGEMM (K=128), fp16 C output, fused a_src/a_dst epilogue ----------------
template<int NC, bool ELU>
__global__ __launch_bounds__(256) void k_gemm(const float* __restrict__ A,
                                              const float* __restrict__ W,
                                              const float* __restrict__ abias,
                                              const float* __restrict__ atts,
                                              const float* __restrict__ attd,
                                              __half* __restrict__ C,
                                              float* __restrict__ oasrc,
                                              float* __restrict__ oadst, int M){
    constexpr int CPT = NC/16;                 // cols per thread (8 or 4)
    __shared__ float As[64*36];
    __shared__ float Ws[32*NC];
    __shared__ float as_s[NC], ad_s[NC];
    const int t  = threadIdx.x;
    const int rg = t >> 4, cg = t & 15;
    const int r0 = blockIdx.x * 64;
    if(t < NC){ as_s[t]=__ldg(&atts[t]); ad_s[t]=__ldg(&attd[t]); }
    float acc[4][CPT];
#pragma unroll
    for(int i=0;i<4;i++)
#pragma unroll
        for(int j=0;j<CPT;j++) acc[i][j]=0.f;

    for(int kc=0; kc<128; kc+=32){
#pragma unroll
        for(int i=0;i<2;i++){
            int f = t + i*256; int r = f>>3; int c4 = f&7;
            float4 v = make_float4(0.f,0.f,0.f,0.f);
            if(r0 + r < M) v = __ldg((const float4*)&A[(size_t)(r0+r)*128 + kc + c4*4]);
            if(ELU){
                float4 bb = __ldg((const float4*)&abias[kc + c4*4]);
                v.x += bb.x; v.y += bb.y; v.z += bb.z; v.w += bb.w;
                v.x = v.x>0.f ? v.x : expm1f(v.x);
                v.y = v.y>0.f ? v.y : expm1f(v.y);
                v.z = v.z>0.f ? v.z : expm1f(v.z);
                v.w = v.w>0.f ? v.w : expm1f(v.w);
            }
            float* dst = &As[r*36 + c4*4];
            dst[0]=v.x; dst[1]=v.y; dst[2]=v.z; dst[3]=v.w;
        }
#pragma unroll
        for(int f=t; f < 32*NC/4; f += 256){
            int k = f/(NC/4); int c = f%(NC/4);
            *(float4*)&Ws[k*NC + c*4] = __ldg((const float4*)&W[(size_t)(kc+k)*NC + c*4]);
        }
        __syncthreads();
#pragma unroll 4
        for(int kk=0; kk<32; kk++){
            float a0 = As[(rg*4+0)*36+kk];
            float a1 = As[(rg*4+1)*36+kk];
            float a2 = As[(rg*4+2)*36+kk];
            float a3 = As[(rg*4+3)*36+kk];
            float4 b0 = *(const float4*)&Ws[kk*NC + cg*CPT];
            acc[0][0]+=a0*b0.x; acc[0][1]+=a0*b0.y; acc[0][2]+=a0*b0.z; acc[0][3]+=a0*b0.w;
            acc[1][0]+=a1*b0.x; acc[1][1]+=a1*b0.y; acc[1][2]+=a1*b0.z; acc[1][3]+=a1*b0.w;
            acc[2][0]+=a2*b0.x; acc[2][1]+=a2*b0.y; acc[2][2]+=a2*b0.z; acc[2][3]+=a2*b0.w;
            acc[3][0]+=a3*b0.x; acc[3][1]+=a3*b0.y; acc[3][2]+=a3*b0.z; acc[3][3]+=a3*b0.w;
            if constexpr (CPT == 8){
                float4 b1 = *(const float4*)&Ws[kk*NC + cg*CPT + 4];
                acc[0][4]+=a0*b1.x; acc[0][5]+=a0*b1.y; acc[0][6]+=a0*b1.z; acc[0][7]+=a0*b1.w;
                acc[1][4]+=a1*b1.x; acc[1][5]+=a1*b1.y; acc[1][6]+=a1*b1.z; acc[1][7]+=a1*b1.w;
                acc[2][4]+=a2*b1.x; acc[2][5]+=a2*b1.y; acc[2][6]+=a2*b1.z; acc[2][7]+=a2*b1.w;
                acc[3][4]+=a3*b1.x; acc[3][5]+=a3*b1.y; acc[3][6]+=a3*b1.z; acc[3][7]+=a3*b1.w;
            }
        }
        __syncthreads();
    }
#pragma unroll
    for(int i=0;i<4;i++){
        int row = r0 + rg*4 + i;
        float ps=0.f, pd=0.f;
#pragma unroll
        for(int j=0;j<CPT;j++){
            float a = acc[i][j];
            ps += a*as_s[cg*CPT+j]; pd += a*ad_s[cg*CPT+j];
        }
        if constexpr (NC == 128){
            ps += __shfl_xor_sync(0xffffffffu, ps, 1); pd += __shfl_xor_sync(0xffffffffu, pd, 1);
            ps += __shfl_xor_sync(0xffffffffu, ps, 2); pd += __shfl_xor_sync(0xffffffffu, pd, 2);
            if((cg&3)==0 && row<M){ oasrc[row*4+(cg>>2)]=ps; oadst[row*4+(cg>>2)]=pd; }
        } else {
            ps += __shfl_xor_sync(0xffffffffu, ps, 1); pd += __shfl_xor_sync(0xffffffffu, pd, 1);
            ps += __shfl_xor_sync(0xffffffffu, ps, 2); pd += __shfl_xor_sync(0xffffffffu, pd, 2);
            ps += __shfl_xor_sync(0xffffffffu, ps, 4); pd += __shfl_xor_sync(0xffffffffu, pd, 4);
            ps += __shfl_xor_sync(0xffffffffu, ps, 8); pd += __shfl_xor_sync(0xffffffffu, pd, 8);
            if(cg==0 && row<M){ oasrc[row]=ps; oadst[row]=pd; }
        }
        if(row < M){
            // convert to half and store
            __half2 hh[CPT/2];
#pragma unroll
            for(int j=0;j<CPT/2;j++)
                hh[j] = __float22half2_rn(make_float2(acc[i][2*j], acc[i][2*j+1]));
            if constexpr (CPT == 8)
                *(uint4*)&C[(size_t)row*NC + cg*CPT] = *(uint4*)hh;
            else
                *(uint2*)&C[(size_t)row*NC + cg*CPT] = *(uint2*)hh;
        }
    }
}

// ---------------- 6. fused layer-1: online softmax + aggregate (warp/node, x4 unroll) ----------------
#define COMB1(a, hv) { \
    if((a) <= m){ float w=__expf((a)-m); sden+=w; \
        acc.x+=hv.x*w; acc.y+=hv.y*w; acc.z+=hv.z*w; acc.w+=hv.w*w; } \
    else { float sc=__expf(m-(a)); sden=sden*sc+1.f; \
        acc.x=acc.x*sc+hv.x; acc.y=acc.y*sc+hv.y; acc.z=acc.z*sc+hv.z; acc.w=acc.w*sc+hv.w; m=(a);} }

__global__ __launch_bounds__(256) void k_layer1(){
    int lane = threadIdx.x & 31;
    int d = (blockIdx.x*blockDim.x + threadIdx.x) >> 5;
    if(d >= Nn) return;
    int beg = g_off[d], end = g_off[d+1];
    int h = lane >> 3;
    float adst = __ldg(&g_adst1[d*4+h]);
    float m = -1e30f, sden = 0.f;
    float4 acc = make_float4(0.f,0.f,0.f,0.f);
    int i = beg;
    for(; i+4 <= end; i+=4){
        int s0=__ldg(&g_ssrc[i+0]), s1=__ldg(&g_ssrc[i+1]),
            s2=__ldg(&g_ssrc[i+2]), s3=__ldg(&g_ssrc[i+3]);
        float e0=__ldg(&g_sae1[(size_t)(i+0)*4+h]), e1=__ldg(&g_sae1[(size_t)(i+1)*4+h]),
              e2=__ldg(&g_sae1[(size_t)(i+2)*4+h]), e3=__ldg(&g_sae1[(size_t)(i+3)*4+h]);
        float a0=lrelu(__ldg(&g_asrc1[s0*4+h])+adst+e0);
        float a1=lrelu(__ldg(&g_asrc1[s1*4+h])+adst+e1);
        float a2=lrelu(__ldg(&g_asrc1[s2*4+h])+adst+e2);
        float a3=lrelu(__ldg(&g_asrc1[s3*4+h])+adst+e3);
        float4 v0=ldh4(&g_h1[(size_t)s0*128+lane*4]);
        float4 v1=ldh4(&g_h1[(size_t)s1*128+lane*4]);
        float4 v2=ldh4(&g_h1[(size_t)s2*128+lane*4]);
        float4 v3=ldh4(&g_h1[(size_t)s3*128+lane*4]);
        COMB1(a0,v0); COMB1(a1,v1); COMB1(a2,v2); COMB1(a3,v3);
    }
    for(; i<end; i++){
        int s = __ldg(&g_ssrc[i]);
        float a = lrelu(__ldg(&g_asrc1[s*4+h])+adst+__ldg(&g_sae1[(size_t)i*4+h]));
        float4 hv = ldh4(&g_h1[(size_t)s*128+lane*4]);
        COMB1(a,hv);
    }
    float inv = 1.f/sden;
    *(float4*)&g_out1[(size_t)d*128 + lane*4] =
        make_float4(acc.x*inv, acc.y*inv, acc.z*inv, acc.w*inv);
}

// ---------------- 7. fused layer-2 + pool (warp/node, x4 unroll) ----------------
#define COMB2(a, hv) { \
    if((a) <= m){ float w=__expf((a)-m); sden+=w; acc.x+=hv.x*w; acc.y+=hv.y*w; } \
    else { float sc=__expf(m-(a)); sden=sden*sc+1.f; \
        acc.x=acc.x*sc+hv.x; acc.y=acc.y*sc+hv.y; m=(a);} }

__global__ __launch_bounds__(256) void k_layer2(const int* __restrict__ batch){
    int lane = threadIdx.x & 31;
    int d = (blockIdx.x*blockDim.x + threadIdx.x) >> 5;
    if(d >= Nn) return;
    int beg = g_off[d], end = g_off[d+1];
    float adst = __ldg(&g_adst2[d]);
    float m = -1e30f, sden = 0.f;
    float2 acc = make_float2(0.f,0.f);
    int i = beg;
    for(; i+4 <= end; i+=4){
        int s0=__ldg(&g_ssrc[i+0]), s1=__ldg(&g_ssrc[i+1]),
            s2=__ldg(&g_ssrc[i+2]), s3=__ldg(&g_ssrc[i+3]);
        float a0=lrelu(__ldg(&g_asrc2[s0])+adst+__ldg(&g_sae2[i+0]));
        float a1=lrelu(__ldg(&g_asrc2[s1])+adst+__ldg(&g_sae2[i+1]));
        float a2=lrelu(__ldg(&g_asrc2[s2])+adst+__ldg(&g_sae2[i+2]));
        float a3=lrelu(__ldg(&g_asrc2[s3])+adst+__ldg(&g_sae2[i+3]));
        float2 v0=ldh2(&g_h2[(size_t)s0*64+lane*2]);
        float2 v1=ldh2(&g_h2[(size_t)s1*64+lane*2]);
        float2 v2=ldh2(&g_h2[(size_t)s2*64+lane*2]);
        float2 v3=ldh2(&g_h2[(size_t)s3*64+lane*2]);
        COMB2(a0,v0); COMB2(a1,v1); COMB2(a2,v2); COMB2(a3,v3);
    }
    for(; i<end; i++){
        int s = __ldg(&g_ssrc[i]);
        float a = lrelu(__ldg(&g_asrc2[s])+adst+__ldg(&g_sae2[i]));
        float2 hv = ldh2(&g_h2[(size_t)s*64+lane*2]);
        COMB2(a,hv);
    }
    float inv = 1.f/sden;
    int g = __ldg(&batch[d]);
    atomicAdd((float2*)&g_pool[g*64 + lane*2], make_float2(acc.x*inv, acc.y*inv));
    if(lane==0) atomicAdd(&g_cnt[g], 1);
}

// ---------------- 8. final: mean + bias ----------------
__global__ void k_final(float* __restrict__ out, const float* __restrict__ b2){
    int i = blockIdx.x*blockDim.x + threadIdx.x;
    if(i >= Gg*64) return;
    out[i] = g_pool[i] / fmaxf((float)g_cnt[i >> 6], 1.0f) + __ldg(&b2[i & 63]);
}

// ---------------- host launcher ----------------
extern "C" void kernel_launch(void* const* d_in, const int* in_sizes, int n_in,
                              void* d_out, int out_size){
    (void)in_sizes; (void)n_in; (void)out_size;
    const float* x     = (const float*)d_in[0];
    const int*   ei    = (const int*)d_in[1];
    const float* ea    = (const float*)d_in[2];
    const int*   batch = (const int*)d_in[3];
    const float* W1    = (const float*)d_in[4];
    const float* as1   = (const float*)d_in[5];
    const float* ad1   = (const float*)d_in[6];
    const float* We1   = (const float*)d_in[7];
    const float* ae1   = (const float*)d_in[8];
    const float* b1    = (const float*)d_in[9];
    const float* W2    = (const float*)d_in[10];
    const float* as2   = (const float*)d_in[11];
    const float* ad2   = (const float*)d_in[12];
    const float* We2   = (const float*)d_in[13];
    const float* ae2   = (const float*)d_in[14];
    const float* b2    = (const float*)d_in[15];
    float*       out   = (float*)d_out;

    void *p_deg,*p_cur,*p_sum,*p_pool,*p_cnt,*p_h1,*p_out1,*p_h2;
    void *p_asrc1,*p_adst1,*p_asrc2,*p_adst2;
    cudaGetSymbolAddress(&p_deg,  g_deg);
    cudaGetSymbolAddress(&p_cur,  g_cur);
    cudaGetSymbolAddress(&p_sum,  g_sum_ea);
    cudaGetSymbolAddress(&p_pool, g_pool);
    cudaGetSymbolAddress(&p_cnt,  g_cnt);
    cudaGetSymbolAddress(&p_h1,   g_h1);
    cudaGetSymbolAddress(&p_out1, g_out1);
    cudaGetSymbolAddress(&p_h2,   g_h2);
    cudaGetSymbolAddress(&p_asrc1, g_asrc1);
    cudaGetSymbolAddress(&p_adst1, g_adst1);
    cudaGetSymbolAddress(&p_asrc2, g_asrc2);
    cudaGetSymbolAddress(&p_adst2, g_adst2);

    cudaStream_t s2;
    cudaEvent_t evFork, evJoin;
    cudaStreamCreateWithFlags(&s2, cudaStreamNonBlocking);
    cudaEventCreateWithFlags(&evFork, cudaEventDisableTiming);
    cudaEventCreateWithFlags(&evJoin, cudaEventDisableTiming);

    cudaMemsetAsync(p_deg, 0, Nn*sizeof(int));
    cudaMemsetAsync(p_cur, 0, Nn*sizeof(int));
    cudaMemsetAsync(p_sum, 0, 16*sizeof(float));
    cudaMemsetAsync(p_pool,0, Gg*64*sizeof(float));
    cudaMemsetAsync(p_cnt, 0, Gg*sizeof(int));

    // fork: GEMM1 runs concurrently with edge preprocessing
    cudaEventRecord(evFork, 0);
    cudaStreamWaitEvent(s2, evFork, 0);
    k_gemm<128,false><<<(Nn+63)/64, 256, 0, s2>>>(x, W1, nullptr, as1, ad1,
                                           (__half*)p_h1, (float*)p_asrc1, (float*)p_adst1, Nn);
    cudaEventRecord(evJoin, s2);

    // edge preprocessing on origin stream
    k_v<<<1, 64>>>(We1, ae1, We2, ae2);
    k_pass1<<<592, 256>>>(ea, ei);
    k_scanA<<<NBLK, 256>>>();
    k_scanB<<<1, 32>>>();
    k_scanC<<<NBLK, 256>>>();
    k_scatter<<<(EPt+255)/256, 256>>>(ei);

    // join: layer1 needs both gemm1 (h1/asrc1/adst1) and scatter (CSR)
    cudaStreamWaitEvent(0, evJoin, 0);
    k_layer1<<<(Nn*32+255)/256, 256>>>();

    k_gemm<64,true><<<(Nn+63)/64, 256>>>((float*)p_out1, W2, b1, as2, ad2,
                                         (__half*)p_h2, (float*)p_asrc2, (float*)p_adst2, Nn);
    k_layer2<<<(Nn*32+255)/256, 256>>>(batch);

    k_final<<<(Gg*64+255)/256, 256>>>(out, b2);
}